// round 16
// baseline (speedup 1.0000x reference)
#include <cuda_runtime.h>
#include <cuda_fp16.h>
#include <math.h>
#include <stdint.h>

#define SLEN 2048
#define TLEN 1024
#define NB   32
#define HID  1024
#define LDA  (NB * HID)

// ---------------------------------------------------------------------------
// Static scratch (no runtime allocation) — all fp16.
// ---------------------------------------------------------------------------
__device__ __half g_enc16_hi[(size_t)SLEN * NB * HID];
__device__ __half g_enc16_lo[(size_t)SLEN * NB * HID];
__device__ __half g_dec16_hi[(size_t)TLEN * NB * HID];
__device__ __half g_dec16_lo[(size_t)TLEN * NB * HID];
__device__ __half g_W16     [(size_t)HID * 2 * HID];
__device__ __half g_attn16  [(size_t)NB * TLEN * SLEN];
__device__ __half g_ctx16   [(size_t)TLEN * NB * HID];   // [m=t*NB+b][h]

// ---------------------------------------------------------------------------
// Dtype-robust src_length read (int32[NB] or int64[NB]; word[1]==0 <=> int64)
// ---------------------------------------------------------------------------
__device__ __forceinline__ int read_len(const int* __restrict__ slen32, int b) {
    const bool is64 = (slen32[1] == 0);
    int len = is64 ? slen32[2 * b] : slen32[b];
    if (len < 1) len = 1;
    if (len > SLEN) len = SLEN;
    return len;
}

// ---------------------------------------------------------------------------
// Split kernels: fp32 -> fp16 hi (+ lo residual)
// ---------------------------------------------------------------------------
__global__ void split_hl(const float4* __restrict__ x, __half2* __restrict__ h16,
                         __half2* __restrict__ l16, int n4)
{
    int i = blockIdx.x * blockDim.x + threadIdx.x;
    if (i >= n4) return;
    float4 v = x[i];
    __half p0 = __float2half(v.x), p1 = __float2half(v.y);
    __half p2 = __float2half(v.z), p3 = __float2half(v.w);
    h16[2 * i]     = __halves2half2(p0, p1);
    h16[2 * i + 1] = __halves2half2(p2, p3);
    l16[2 * i] = __halves2half2(__float2half(v.x - __half2float(p0)),
                                __float2half(v.y - __half2float(p1)));
    l16[2 * i + 1] = __halves2half2(__float2half(v.z - __half2float(p2)),
                                    __float2half(v.w - __half2float(p3)));
}

__global__ void split_h(const float4* __restrict__ x, __half2* __restrict__ h16, int n4)
{
    int i = blockIdx.x * blockDim.x + threadIdx.x;
    if (i >= n4) return;
    float4 v = x[i];
    h16[2 * i]     = __halves2half2(__float2half(v.x), __float2half(v.y));
    h16[2 * i + 1] = __halves2half2(__float2half(v.z), __float2half(v.w));
}

// ---------------------------------------------------------------------------
// Primitives
// ---------------------------------------------------------------------------
__device__ __forceinline__ unsigned smem_u32(const void* p) {
    return (unsigned)__cvta_generic_to_shared(p);
}
__device__ __forceinline__ void cp16(unsigned dst, const void* src) {
    asm volatile("cp.async.cg.shared.global [%0], [%1], 16;" :: "r"(dst), "l"(src));
}
__device__ __forceinline__ void cp_commit() {
    asm volatile("cp.async.commit_group;" ::: "memory");
}
template <int N>
__device__ __forceinline__ void cp_wait() {
    asm volatile("cp.async.wait_group %0;" :: "n"(N) : "memory");
}

__device__ __forceinline__ void ldsm4(unsigned addr,
    unsigned& r0, unsigned& r1, unsigned& r2, unsigned& r3)
{
    asm volatile("ldmatrix.sync.aligned.m8n8.x4.shared.b16 {%0,%1,%2,%3}, [%4];"
        : "=r"(r0), "=r"(r1), "=r"(r2), "=r"(r3) : "r"(addr));
}
__device__ __forceinline__ void ldsm4t(unsigned addr,
    unsigned& r0, unsigned& r1, unsigned& r2, unsigned& r3)
{
    asm volatile("ldmatrix.sync.aligned.m8n8.x4.trans.shared.b16 {%0,%1,%2,%3}, [%4];"
        : "=r"(r0), "=r"(r1), "=r"(r2), "=r"(r3) : "r"(addr));
}
__device__ __forceinline__ void mma_f16(float c[4],
    unsigned a0, unsigned a1, unsigned a2, unsigned a3, unsigned b0, unsigned b1)
{
    asm volatile(
        "mma.sync.aligned.m16n8k16.row.col.f32.f16.f16.f32 "
        "{%0,%1,%2,%3}, {%4,%5,%6,%7}, {%8,%9}, {%0,%1,%2,%3};"
        : "+f"(c[0]), "+f"(c[1]), "+f"(c[2]), "+f"(c[3])
        : "r"(a0), "r"(a1), "r"(a2), "r"(a3), "r"(b0), "r"(b1));
}

// Tile strides in elements (padded; conflict-free for ldmatrix)
#define ASTR 40     // [row][32k]: 80B rows
#define BKSTR 136   // [32k][128n]: 272B rows

// GEMM1 (NEW 128x64 tile): A 128x32 hi/lo + B 64x32 hi/lo, double-buffered
#define U_AH 0
#define U_AL 10240
#define U_BH 20480
#define U_BL 25600
#define STG1 30720
// GEMM2 stage (A hi + trans-B), double-buffered
#define S2_B 10240
#define STG2 18944
// GEMM3 stage (A hi + k-contig B), double-buffered
#define S3_B 10240
#define STG3 20480

// ---------------------------------------------------------------------------
// cp.async tile loaders (2-byte elements)
// ---------------------------------------------------------------------------
__device__ __forceinline__ void cpa_nt(unsigned sb, const void* __restrict__ g,
                                       size_t ld, int tid)
{
    const uint16_t* p = (const uint16_t*)g;
#pragma unroll
    for (int l = 0; l < 2; ++l) {
        int idx = tid + l * 256;
        int r = idx >> 2, q = idx & 3;
        cp16(sb + (unsigned)(r * ASTR + q * 8) * 2, p + (size_t)r * ld + q * 8);
    }
}
// [64 rows][32 k] tile: one cp16 per thread (256 threads)
__device__ __forceinline__ void cpa_nt64(unsigned sb, const void* __restrict__ g,
                                         size_t ld, int tid)
{
    const uint16_t* p = (const uint16_t*)g;
    int r = tid >> 2, q = tid & 3;
    cp16(sb + (unsigned)(r * ASTR + q * 8) * 2, p + (size_t)r * ld + q * 8);
}
__device__ __forceinline__ void cpa_tr(unsigned sb, const void* __restrict__ g,
                                       size_t ld, int tid)
{
    const uint16_t* p = (const uint16_t*)g;
#pragma unroll
    for (int l = 0; l < 2; ++l) {
        int idx = tid + l * 256;
        int r = idx >> 4, q = idx & 15;
        cp16(sb + (unsigned)(r * BKSTR + q * 8) * 2, p + (size_t)r * ld + q * 8);
    }
}

// ---------------------------------------------------------------------------
// 3-term chunk, warp tile 32x32 (MI=2 m-tiles): for the 128x64 GEMM1.
// Same per-accumulator term order (hh, hl, lh) -> bit-identical results.
// ---------------------------------------------------------------------------
__device__ __forceinline__ void mma_chunk3_m2(
    const void* As_hi, const void* As_lo,
    const void* Bs_hi, const void* Bs_lo,
    float acc[2][4][4], int lane, int m_base, int n_base)
{
    const int ra = (lane & 7) + ((lane >> 3) & 1) * 8;
    const int ka = (lane >> 4) * 8;
    const int rb = (lane & 7) + (lane >> 4) * 8;
    const int kbo = ((lane >> 3) & 1) * 8;

#pragma unroll
    for (int kk = 0; kk < 32; kk += 16) {
        unsigned ah[2][4], al[2][4], bh[2][4], bl[2][4];
#pragma unroll
        for (int i = 0; i < 2; ++i) {
            unsigned off = ((m_base + 16 * i + ra) * ASTR + kk + ka) * 2;
            ldsm4(smem_u32(As_hi) + off, ah[i][0], ah[i][1], ah[i][2], ah[i][3]);
            ldsm4(smem_u32(As_lo) + off, al[i][0], al[i][1], al[i][2], al[i][3]);
        }
#pragma unroll
        for (int jB = 0; jB < 2; ++jB) {
            unsigned off = ((n_base + 16 * jB + rb) * ASTR + kk + kbo) * 2;
            ldsm4(smem_u32(Bs_hi) + off, bh[jB][0], bh[jB][1], bh[jB][2], bh[jB][3]);
            ldsm4(smem_u32(Bs_lo) + off, bl[jB][0], bl[jB][1], bl[jB][2], bl[jB][3]);
        }
#pragma unroll
        for (int i = 0; i < 2; ++i)
#pragma unroll
            for (int j = 0; j < 4; ++j) {
                const int jB = j >> 1, s = (j & 1) * 2;
                mma_f16(acc[i][j], ah[i][0], ah[i][1], ah[i][2], ah[i][3], bh[jB][s], bh[jB][s + 1]);
                mma_f16(acc[i][j], ah[i][0], ah[i][1], ah[i][2], ah[i][3], bl[jB][s], bl[jB][s + 1]);
                mma_f16(acc[i][j], al[i][0], al[i][1], al[i][2], al[i][3], bh[jB][s], bh[jB][s + 1]);
            }
    }
}

// ---------------------------------------------------------------------------
// 1-term chunk: acc += A.B (hi only). (unchanged; 64x32 warp tile)
// ---------------------------------------------------------------------------
template <bool BT>
__device__ __forceinline__ void mma_chunk1(
    const void* As, const void* Bs,
    float acc[4][4][4], int lane, int m_base, int n_base)
{
    const int ra = (lane & 7) + ((lane >> 3) & 1) * 8;
    const int ka = (lane >> 4) * 8;
    const int rb = (lane & 7) + (lane >> 4) * 8;
    const int kbo = ((lane >> 3) & 1) * 8;
    const int krt = (lane & 7) + ((lane >> 3) & 1) * 8;
    const int nft = (lane >> 4) * 8;

#pragma unroll
    for (int kk = 0; kk < 32; kk += 16) {
        unsigned ah[4][4], bb[2][4];
#pragma unroll
        for (int i = 0; i < 4; ++i) {
            unsigned off = ((m_base + 16 * i + ra) * ASTR + kk + ka) * 2;
            ldsm4(smem_u32(As) + off, ah[i][0], ah[i][1], ah[i][2], ah[i][3]);
        }
#pragma unroll
        for (int jB = 0; jB < 2; ++jB) {
            if (!BT) {
                unsigned off = ((n_base + 16 * jB + rb) * ASTR + kk + kbo) * 2;
                ldsm4(smem_u32(Bs) + off, bb[jB][0], bb[jB][1], bb[jB][2], bb[jB][3]);
            } else {
                unsigned off = ((kk + krt) * BKSTR + n_base + 16 * jB + nft) * 2;
                ldsm4t(smem_u32(Bs) + off, bb[jB][0], bb[jB][1], bb[jB][2], bb[jB][3]);
            }
        }
#pragma unroll
        for (int i = 0; i < 4; ++i)
#pragma unroll
            for (int j = 0; j < 4; ++j) {
                const int jB = j >> 1, s = (j & 1) * 2;
                mma_f16(acc[i][j], ah[i][0], ah[i][1], ah[i][2], ah[i][3], bb[jB][s], bb[jB][s + 1]);
            }
    }
}

// ---------------------------------------------------------------------------
// GEMM1: scores = dec . enc (fp16 3-term). NEW: 128x64 tile, 256 threads,
// warp grid 4m x 2n (warp tile 32x32), ~80 regs -> 3 CTAs/SM (24 warps).
// Fully-masked n-tiles skipped.
// ---------------------------------------------------------------------------
__global__ __launch_bounds__(256, 3)
void gemm1_scores(float* __restrict__ scores, const int* __restrict__ slen32)
{
    extern __shared__ __align__(16) char dsm[];
    const int b = blockIdx.z, m0 = blockIdx.y * 128, n0 = blockIdx.x * 64;

    if (n0 >= read_len(slen32, b)) return;

    const int tid = threadIdx.x, lane = tid & 31, wid = tid >> 5;
    const int m_base = (wid >> 1) * 32, n_base = (wid & 1) * 32;

    const unsigned sb = smem_u32(dsm);
    const unsigned st[2] = { sb, sb + STG1 };

    const __half* Ah = g_dec16_hi + (size_t)m0 * LDA + (size_t)b * HID;
    const __half* Al = g_dec16_lo + (size_t)m0 * LDA + (size_t)b * HID;
    const __half* Bh = g_enc16_hi + (size_t)n0 * LDA + (size_t)b * HID;
    const __half* Bl = g_enc16_lo + (size_t)n0 * LDA + (size_t)b * HID;
    const int NC = HID / 32;

    cpa_nt(st[0] + U_AH, Ah, LDA, tid);
    cpa_nt(st[0] + U_AL, Al, LDA, tid);
    cpa_nt64(st[0] + U_BH, Bh, LDA, tid);
    cpa_nt64(st[0] + U_BL, Bl, LDA, tid);
    cp_commit();

    float acc[2][4][4] = {};
    for (int m = 0; m < NC; ++m) {
        const int s = m & 1;
        if (m + 1 < NC) {
            const int j = (m + 1) & 1;
            const size_t kb = (size_t)(m + 1) * 32;
            cpa_nt(st[j] + U_AH, Ah + kb, LDA, tid);
            cpa_nt(st[j] + U_AL, Al + kb, LDA, tid);
            cpa_nt64(st[j] + U_BH, Bh + kb, LDA, tid);
            cpa_nt64(st[j] + U_BL, Bl + kb, LDA, tid);
            cp_commit();
            cp_wait<1>();
        } else {
            cp_wait<0>();
        }
        __syncthreads();
        mma_chunk3_m2(dsm + (st[s] - sb) + U_AH, dsm + (st[s] - sb) + U_AL,
                      dsm + (st[s] - sb) + U_BH, dsm + (st[s] - sb) + U_BL,
                      acc, lane, m_base, n_base);
        __syncthreads();
    }

    float* C = scores + (size_t)b * TLEN * SLEN;
    const int r0 = lane >> 2, c0 = (lane & 3) * 2;
#pragma unroll
    for (int i = 0; i < 2; ++i)
#pragma unroll
        for (int j = 0; j < 4; ++j) {
            const int row = m0 + m_base + 16 * i + r0;
            const int col = n0 + n_base + 8 * j + c0;
            *reinterpret_cast<float2*>(C + (size_t)row * SLEN + col)
                = make_float2(acc[i][j][0], acc[i][j][1]);
            *reinterpret_cast<float2*>(C + (size_t)(row + 8) * SLEN + col)
                = make_float2(acc[i][j][2], acc[i][j][3]);
        }
}

// ---------------------------------------------------------------------------
// Masked softmax over S, in place; emits fp16 attn (hi only).
// Shuffle-based reductions; masked upper half-row loads skipped.
// ---------------------------------------------------------------------------
__global__ __launch_bounds__(256)
void softmax_rows(float* __restrict__ scores, const int* __restrict__ slen32)
{
    __shared__ float red[8];
    __shared__ int s_len;

    const int row = blockIdx.x;
    const int b = row / TLEN;
    const int tid = threadIdx.x;
    const int lane = tid & 31, wrp = tid >> 5;

    if (tid == 0) s_len = read_len(slen32, b);
    __syncthreads();
    const int len = s_len;

    float* p = scores + (size_t)row * SLEN;
    float4 v0 = reinterpret_cast<const float4*>(p)[tid];
    float4 v1 = ((tid + 256) * 4 < len)
                ? reinterpret_cast<const float4*>(p)[tid + 256]
                : make_float4(0.f, 0.f, 0.f, 0.f);

    float e[8] = { v0.x, v0.y, v0.z, v0.w, v1.x, v1.y, v1.z, v1.w };
    int s[8];
#pragma unroll
    for (int q = 0; q < 4; ++q) { s[q] = tid * 4 + q; s[4 + q] = (tid + 256) * 4 + q; }

    float m = -1e30f;
#pragma unroll
    for (int q = 0; q < 8; ++q) if (s[q] < len) m = fmaxf(m, e[q]);
#pragma unroll
    for (int off = 16; off > 0; off >>= 1)
        m = fmaxf(m, __shfl_xor_sync(0xffffffffu, m, off));
    if (lane == 0) red[wrp] = m;
    __syncthreads();
    float rowmax = red[lane & 7];
#pragma unroll
    for (int off = 4; off > 0; off >>= 1)
        rowmax = fmaxf(rowmax, __shfl_xor_sync(0xffffffffu, rowmax, off));
    rowmax = __shfl_sync(0xffffffffu, rowmax, 0);

    float sum = 0.f;
#pragma unroll
    for (int q = 0; q < 8; ++q) {
        float ev = (s[q] < len) ? __expf(e[q] - rowmax) : 0.f;
        e[q] = ev; sum += ev;
    }
#pragma unroll
    for (int off = 16; off > 0; off >>= 1)
        sum += __shfl_xor_sync(0xffffffffu, sum, off);
    __syncthreads();
    if (lane == 0) red[wrp] = sum;
    __syncthreads();
    float tot = red[lane & 7];
#pragma unroll
    for (int off = 4; off > 0; off >>= 1)
        tot += __shfl_xor_sync(0xffffffffu, tot, off);
    tot = __shfl_sync(0xffffffffu, tot, 0);
    const float inv = 1.f / tot;

#pragma unroll
    for (int q = 0; q < 8; ++q) e[q] *= inv;

    reinterpret_cast<float4*>(p)[tid]       = make_float4(e[0], e[1], e[2], e[3]);
    reinterpret_cast<float4*>(p)[tid + 256] = make_float4(e[4], e[5], e[6], e[7]);

    __half2* ph = reinterpret_cast<__half2*>(g_attn16 + (size_t)row * SLEN);
#pragma unroll
    for (int h = 0; h < 2; ++h) {
        const int base = (h == 0) ? tid * 2 : (tid + 256) * 2;
        const int qb = h * 4;
        ph[base]     = __halves2half2(__float2half(e[qb + 0]), __float2half(e[qb + 1]));
        ph[base + 1] = __halves2half2(__float2half(e[qb + 2]), __float2half(e[qb + 3]));
    }
}

// ---------------------------------------------------------------------------
// GEMM2: ctx = attn . enc (fp16 1-term). K=32 chunks, double-buffered;
// K truncated at ceil(len/32).
// ---------------------------------------------------------------------------
__global__ __launch_bounds__(256, 2)
void gemm2_ctx(const int* __restrict__ slen32)
{
    extern __shared__ __align__(16) char dsm[];
    const int b = blockIdx.z, m0 = blockIdx.y * 128, n0 = blockIdx.x * 128;
    const int tid = threadIdx.x, lane = tid & 31, wid = tid >> 5;
    const int m_base = (wid >> 2) * 64, n_base = (wid & 3) * 32;

    const unsigned sb = smem_u32(dsm);
    const unsigned st[2] = { sb, sb + STG2 };

    const __half* Av = g_attn16 + (size_t)b * TLEN * SLEN + (size_t)m0 * SLEN;
    const __half* Bv = g_enc16_hi + (size_t)b * HID + n0;
    const int NC = (read_len(slen32, b) + 31) / 32;

    cpa_nt(st[0], Av, SLEN, tid);
    cpa_tr(st[0] + S2_B, Bv, LDA, tid);
    cp_commit();

    float acc[4][4][4] = {};
    for (int m = 0; m < NC; ++m) {
        const int s = m & 1;
        if (m + 1 < NC) {
            const int j = (m + 1) & 1;
            const size_t kb = (size_t)(m + 1) * 32;
            cpa_nt(st[j], Av + kb, SLEN, tid);
            cpa_tr(st[j] + S2_B, Bv + kb * LDA, LDA, tid);
            cp_commit();
            cp_wait<1>();
        } else {
            cp_wait<0>();
        }
        __syncthreads();
        mma_chunk1<true>(dsm + (st[s] - sb), dsm + (st[s] - sb) + S2_B,
                         acc, lane, m_base, n_base);
        __syncthreads();
    }

    const int r0 = lane >> 2, c0 = (lane & 3) * 2;
#pragma unroll
    for (int i = 0; i < 4; ++i)
#pragma unroll
        for (int j = 0; j < 4; ++j) {
            const int mrow = m0 + m_base + 16 * i + r0;
            const int col = n0 + n_base + 8 * j + c0;
#pragma unroll
            for (int hh = 0; hh < 2; ++hh) {
                const size_t off = (size_t)b * HID + (size_t)(mrow + 8 * hh) * LDA + col;
                *reinterpret_cast<__half2*>(g_ctx16 + off) = __halves2half2(
                    __float2half(acc[i][j][2 * hh]), __float2half(acc[i][j][2 * hh + 1]));
            }
        }
}

// ---------------------------------------------------------------------------
// GEMM3: states = tanh(concat(ctx,dec) . W^T + bias) (fp16 1-term,
// K=32 chunks, double-buffered)
// ---------------------------------------------------------------------------
__global__ __launch_bounds__(256, 2)
void gemm3_out(const float* __restrict__ bias, float* __restrict__ outp)
{
    extern __shared__ __align__(16) char dsm[];
    const int m0 = blockIdx.y * 128, n0 = blockIdx.x * 128;
    const int tid = threadIdx.x, lane = tid & 31, wid = tid >> 5;
    const int m_base = (wid >> 2) * 64, n_base = (wid & 3) * 32;

    const unsigned sb = smem_u32(dsm);
    const unsigned st[2] = { sb, sb + STG3 };

    const __half* Ctx = g_ctx16 + (size_t)m0 * HID;
    const __half* Dec = g_dec16_hi + (size_t)m0 * HID;
    const __half* Bv = g_W16 + (size_t)n0 * (2 * HID);
    const int NC = (2 * HID) / 32;

    cpa_nt(st[0], Ctx, HID, tid);
    cpa_nt(st[0] + S3_B, Bv, 2 * HID, tid);
    cp_commit();

    float acc[4][4][4] = {};
    for (int m = 0; m < NC; ++m) {
        const int s = m & 1;
        if (m + 1 < NC) {
            const int j = (m + 1) & 1;
            const int kb = (m + 1) * 32;
            const __half* pa = (kb < HID) ? (Ctx + kb) : (Dec + (kb - HID));
            cpa_nt(st[j], pa, HID, tid);
            cpa_nt(st[j] + S3_B, Bv + kb, 2 * HID, tid);
            cp_commit();
            cp_wait<1>();
        } else {
            cp_wait<0>();
        }
        __syncthreads();
        mma_chunk1<false>(dsm + (st[s] - sb), dsm + (st[s] - sb) + S3_B,
                          acc, lane, m_base, n_base);
        __syncthreads();
    }

    const int r0 = lane >> 2, c0 = (lane & 3) * 2;
#pragma unroll
    for (int i = 0; i < 4; ++i)
#pragma unroll
        for (int j = 0; j < 4; ++j) {
            const int row = m0 + m_base + 16 * i + r0;
            const int col = n0 + n_base + 8 * j + c0;
            const float b0 = bias[col], b1 = bias[col + 1];
            *reinterpret_cast<float2*>(outp + (size_t)row * HID + col)
                = make_float2(tanhf(acc[i][j][0] + b0), tanhf(acc[i][j][1] + b1));
            *reinterpret_cast<float2*>(outp + (size_t)(row + 8) * HID + col)
                = make_float2(tanhf(acc[i][j][2] + b0), tanhf(acc[i][j][3] + b1));
        }
}

// ---------------------------------------------------------------------------
// kernel_launch — inputs identified by element count (order-proof)
// ---------------------------------------------------------------------------
extern "C" void kernel_launch(void* const* d_in, const int* in_sizes, int n_in,
                              void* d_out, int out_size)
{
    const float* ctxt = nullptr;
    const int*   slen = nullptr;
    const float* dec  = nullptr;
    const float* W    = nullptr;
    const float* bias = nullptr;

    for (int i = 0; i < n_in; ++i) {
        switch (in_sizes[i]) {
            case SLEN * NB * HID: ctxt = (const float*)d_in[i]; break;
            case TLEN * NB * HID: dec  = (const float*)d_in[i]; break;
            case HID * 2 * HID:   W    = (const float*)d_in[i]; break;
            case HID:             bias = (const float*)d_in[i]; break;
            case NB:              slen = (const int*)d_in[i];   break;
        }
    }

    float* outp   = (float*)d_out;
    float* states = outp;                              // [T,B,H]
    float* attn   = outp + (size_t)TLEN * NB * HID;    // [B,T,S]

    const int smem_g1 = 2 * STG1;  // 61440
    const int smem_g2 = 2 * STG2;  // 37888
    const int smem_g3 = 2 * STG3;  // 40960
    cudaFuncSetAttribute(gemm1_scores, cudaFuncAttributeMaxDynamicSharedMemorySize, smem_g1);
    cudaFuncSetAttribute(gemm2_ctx,    cudaFuncAttributeMaxDynamicSharedMemorySize, smem_g2);
    cudaFuncSetAttribute(gemm3_out,    cudaFuncAttributeMaxDynamicSharedMemorySize, smem_g3);

    __half *enc_h, *enc_l, *dec_h, *dec_l, *w16;
    cudaGetSymbolAddress((void**)&enc_h, g_enc16_hi);
    cudaGetSymbolAddress((void**)&enc_l, g_enc16_lo);
    cudaGetSymbolAddress((void**)&dec_h, g_dec16_hi);
    cudaGetSymbolAddress((void**)&dec_l, g_dec16_lo);
    cudaGetSymbolAddress((void**)&w16,   g_W16);

    // 1) splits
    {
        int n4 = (SLEN * NB * HID) / 4;
        split_hl<<<n4 / 256, 256>>>((const float4*)ctxt, (__half2*)enc_h, (__half2*)enc_l, n4);
        n4 = (TLEN * NB * HID) / 4;
        split_hl<<<n4 / 256, 256>>>((const float4*)dec, (__half2*)dec_h, (__half2*)dec_l, n4);
        n4 = (HID * 2 * HID) / 4;
        split_h<<<n4 / 256, 256>>>((const float4*)W, (__half2*)w16, n4);
    }

    // 2) scores -> attn region (masked n-tiles skipped); 128x64 tiles, 3 CTAs/SM
    gemm1_scores<<<dim3(SLEN / 64, TLEN / 128, NB), 256, smem_g1>>>(attn, slen);

    // 3) masked softmax in place + attn fp16
    softmax_rows<<<NB * TLEN, 256>>>(attn, slen);

    // 4) ctx = attn @ enc (fp16 1-term; K truncated at src_length)
    gemm2_ctx<<<dim3(HID / 128, TLEN / 128, NB), 256, smem_g2>>>(slen);

    // 5) states = tanh(concat(ctx,dec) @ W^T + b) (fp16 1-term)
    gemm3_out<<<dim3(HID / 128, (TLEN * NB) / 128), 256, smem_g3>>>(bias, states);
}

// round 17
// speedup vs baseline: 1.0077x; 1.0077x over previous
#include <cuda_runtime.h>
#include <cuda_fp16.h>
#include <math.h>
#include <stdint.h>

#define SLEN 2048
#define TLEN 1024
#define NB   32
#define HID  1024
#define LDA  (NB * HID)

// ---------------------------------------------------------------------------
// Static scratch (no runtime allocation) — all fp16.
// GEMM1 (fp16 3-term): enc/dec hi+lo.
// GEMM2 (fp16 1-term): attn hi, enc hi.
// GEMM3 (fp16 1-term): ctx hi, dec hi, W hi.
// ---------------------------------------------------------------------------
__device__ __half g_enc16_hi[(size_t)SLEN * NB * HID];
__device__ __half g_enc16_lo[(size_t)SLEN * NB * HID];
__device__ __half g_dec16_hi[(size_t)TLEN * NB * HID];
__device__ __half g_dec16_lo[(size_t)TLEN * NB * HID];
__device__ __half g_W16     [(size_t)HID * 2 * HID];
__device__ __half g_attn16  [(size_t)NB * TLEN * SLEN];
__device__ __half g_ctx16   [(size_t)TLEN * NB * HID];   // [m=t*NB+b][h]

// ---------------------------------------------------------------------------
// Dtype-robust src_length read (int32[NB] or int64[NB]; word[1]==0 <=> int64)
// ---------------------------------------------------------------------------
__device__ __forceinline__ int read_len(const int* __restrict__ slen32, int b) {
    const bool is64 = (slen32[1] == 0);
    int len = is64 ? slen32[2 * b] : slen32[b];
    if (len < 1) len = 1;
    if (len > SLEN) len = SLEN;
    return len;
}

// ---------------------------------------------------------------------------
// Split kernels: fp32 -> fp16 hi (+ lo residual)
// ---------------------------------------------------------------------------
__global__ void split_hl(const float4* __restrict__ x, __half2* __restrict__ h16,
                         __half2* __restrict__ l16, int n4)
{
    int i = blockIdx.x * blockDim.x + threadIdx.x;
    if (i >= n4) return;
    float4 v = x[i];
    __half p0 = __float2half(v.x), p1 = __float2half(v.y);
    __half p2 = __float2half(v.z), p3 = __float2half(v.w);
    h16[2 * i]     = __halves2half2(p0, p1);
    h16[2 * i + 1] = __halves2half2(p2, p3);
    l16[2 * i] = __halves2half2(__float2half(v.x - __half2float(p0)),
                                __float2half(v.y - __half2float(p1)));
    l16[2 * i + 1] = __halves2half2(__float2half(v.z - __half2float(p2)),
                                    __float2half(v.w - __half2float(p3)));
}

__global__ void split_h(const float4* __restrict__ x, __half2* __restrict__ h16, int n4)
{
    int i = blockIdx.x * blockDim.x + threadIdx.x;
    if (i >= n4) return;
    float4 v = x[i];
    h16[2 * i]     = __halves2half2(__float2half(v.x), __float2half(v.y));
    h16[2 * i + 1] = __halves2half2(__float2half(v.z), __float2half(v.w));
}

// ---------------------------------------------------------------------------
// Primitives
// ---------------------------------------------------------------------------
__device__ __forceinline__ unsigned smem_u32(const void* p) {
    return (unsigned)__cvta_generic_to_shared(p);
}
__device__ __forceinline__ void cp16(unsigned dst, const void* src) {
    asm volatile("cp.async.cg.shared.global [%0], [%1], 16;" :: "r"(dst), "l"(src));
}
__device__ __forceinline__ void cp_commit() {
    asm volatile("cp.async.commit_group;" ::: "memory");
}
template <int N>
__device__ __forceinline__ void cp_wait() {
    asm volatile("cp.async.wait_group %0;" :: "n"(N) : "memory");
}

__device__ __forceinline__ void ldsm4(unsigned addr,
    unsigned& r0, unsigned& r1, unsigned& r2, unsigned& r3)
{
    asm volatile("ldmatrix.sync.aligned.m8n8.x4.shared.b16 {%0,%1,%2,%3}, [%4];"
        : "=r"(r0), "=r"(r1), "=r"(r2), "=r"(r3) : "r"(addr));
}
__device__ __forceinline__ void ldsm4t(unsigned addr,
    unsigned& r0, unsigned& r1, unsigned& r2, unsigned& r3)
{
    asm volatile("ldmatrix.sync.aligned.m8n8.x4.trans.shared.b16 {%0,%1,%2,%3}, [%4];"
        : "=r"(r0), "=r"(r1), "=r"(r2), "=r"(r3) : "r"(addr));
}
__device__ __forceinline__ void mma_f16(float c[4],
    unsigned a0, unsigned a1, unsigned a2, unsigned a3, unsigned b0, unsigned b1)
{
    asm volatile(
        "mma.sync.aligned.m16n8k16.row.col.f32.f16.f16.f32 "
        "{%0,%1,%2,%3}, {%4,%5,%6,%7}, {%8,%9}, {%0,%1,%2,%3};"
        : "+f"(c[0]), "+f"(c[1]), "+f"(c[2]), "+f"(c[3])
        : "r"(a0), "r"(a1), "r"(a2), "r"(a3), "r"(b0), "r"(b1));
}

// Tile strides in elements (padded; conflict-free for ldmatrix)
#define ASTR 40     // [row][32k]: 80B rows
#define BKSTR 136   // [32k][128n]: 272B rows

// GEMM1 stage (A hi/lo + B hi/lo, all 128x32), double-buffered
#define T_AH 0
#define T_AL 10240
#define T_BH 20480
#define T_BL 30720
#define STG1 40960
// GEMM2 stage (A hi + trans-B), double-buffered
#define S2_B 10240
#define STG2 18944
// GEMM3 stage (A hi + k-contig B), double-buffered
#define S3_B 10240
#define STG3 20480

// ---------------------------------------------------------------------------
// cp.async tile loaders (2-byte elements)
// ---------------------------------------------------------------------------
__device__ __forceinline__ void cpa_nt(unsigned sb, const void* __restrict__ g,
                                       size_t ld, int tid)
{
    const uint16_t* p = (const uint16_t*)g;
#pragma unroll
    for (int l = 0; l < 2; ++l) {
        int idx = tid + l * 256;
        int r = idx >> 2, q = idx & 3;
        cp16(sb + (unsigned)(r * ASTR + q * 8) * 2, p + (size_t)r * ld + q * 8);
    }
}
__device__ __forceinline__ void cpa_tr(unsigned sb, const void* __restrict__ g,
                                       size_t ld, int tid)
{
    const uint16_t* p = (const uint16_t*)g;
#pragma unroll
    for (int l = 0; l < 2; ++l) {
        int idx = tid + l * 256;
        int r = idx >> 4, q = idx & 15;
        cp16(sb + (unsigned)(r * BKSTR + q * 8) * 2, p + (size_t)r * ld + q * 8);
    }
}

// ---------------------------------------------------------------------------
// GEMM1 chunk: fp16 3-term (hh, hl, lh)
// ---------------------------------------------------------------------------
__device__ __forceinline__ void mma_chunk3(
    const void* As_hi, const void* As_lo,
    const void* Bs_hi, const void* Bs_lo,
    float acc[4][4][4], int lane, int m_base, int n_base)
{
    const int ra = (lane & 7) + ((lane >> 3) & 1) * 8;
    const int ka = (lane >> 4) * 8;
    const int rb = (lane & 7) + (lane >> 4) * 8;
    const int kbo = ((lane >> 3) & 1) * 8;

#pragma unroll
    for (int kk = 0; kk < 32; kk += 16) {
        unsigned ah[4][4], al[4][4], bh[2][4], bl[2][4];
#pragma unroll
        for (int i = 0; i < 4; ++i) {
            unsigned off = ((m_base + 16 * i + ra) * ASTR + kk + ka) * 2;
            ldsm4(smem_u32(As_hi) + off, ah[i][0], ah[i][1], ah[i][2], ah[i][3]);
            ldsm4(smem_u32(As_lo) + off, al[i][0], al[i][1], al[i][2], al[i][3]);
        }
#pragma unroll
        for (int jB = 0; jB < 2; ++jB) {
            unsigned off = ((n_base + 16 * jB + rb) * ASTR + kk + kbo) * 2;
            ldsm4(smem_u32(Bs_hi) + off, bh[jB][0], bh[jB][1], bh[jB][2], bh[jB][3]);
            ldsm4(smem_u32(Bs_lo) + off, bl[jB][0], bl[jB][1], bl[jB][2], bl[jB][3]);
        }
#pragma unroll
        for (int i = 0; i < 4; ++i)
#pragma unroll
            for (int j = 0; j < 4; ++j) {
                const int jB = j >> 1, s = (j & 1) * 2;
                mma_f16(acc[i][j], ah[i][0], ah[i][1], ah[i][2], ah[i][3], bh[jB][s], bh[jB][s + 1]);
                mma_f16(acc[i][j], ah[i][0], ah[i][1], ah[i][2], ah[i][3], bl[jB][s], bl[jB][s + 1]);
                mma_f16(acc[i][j], al[i][0], al[i][1], al[i][2], al[i][3], bh[jB][s], bh[jB][s + 1]);
            }
    }
}

// ---------------------------------------------------------------------------
// 1-term chunk: acc += A.B (hi only).
// ---------------------------------------------------------------------------
template <bool BT>
__device__ __forceinline__ void mma_chunk1(
    const void* As, const void* Bs,
    float acc[4][4][4], int lane, int m_base, int n_base)
{
    const int ra = (lane & 7) + ((lane >> 3) & 1) * 8;
    const int ka = (lane >> 4) * 8;
    const int rb = (lane & 7) + (lane >> 4) * 8;
    const int kbo = ((lane >> 3) & 1) * 8;
    const int krt = (lane & 7) + ((lane >> 3) & 1) * 8;
    const int nft = (lane >> 4) * 8;

#pragma unroll
    for (int kk = 0; kk < 32; kk += 16) {
        unsigned ah[4][4], bb[2][4];
#pragma unroll
        for (int i = 0; i < 4; ++i) {
            unsigned off = ((m_base + 16 * i + ra) * ASTR + kk + ka) * 2;
            ldsm4(smem_u32(As) + off, ah[i][0], ah[i][1], ah[i][2], ah[i][3]);
        }
#pragma unroll
        for (int jB = 0; jB < 2; ++jB) {
            if (!BT) {
                unsigned off = ((n_base + 16 * jB + rb) * ASTR + kk + kbo) * 2;
                ldsm4(smem_u32(Bs) + off, bb[jB][0], bb[jB][1], bb[jB][2], bb[jB][3]);
            } else {
                unsigned off = ((kk + krt) * BKSTR + n_base + 16 * jB + nft) * 2;
                ldsm4t(smem_u32(Bs) + off, bb[jB][0], bb[jB][1], bb[jB][2], bb[jB][3]);
            }
        }
#pragma unroll
        for (int i = 0; i < 4; ++i)
#pragma unroll
            for (int j = 0; j < 4; ++j) {
                const int jB = j >> 1, s = (j & 1) * 2;
                mma_f16(acc[i][j], ah[i][0], ah[i][1], ah[i][2], ah[i][3], bb[jB][s], bb[jB][s + 1]);
            }
    }
}

// ---------------------------------------------------------------------------
// GEMM1: scores = dec . enc (fp16 3-term). 128x128 tile, 256 threads,
// 2 CTAs/SM, double-buffered K=32 stages. Fully-masked n-tiles skipped.
// ---------------------------------------------------------------------------
__global__ __launch_bounds__(256, 2)
void gemm1_scores(float* __restrict__ scores, const int* __restrict__ slen32)
{
    extern __shared__ __align__(16) char dsm[];
    const int b = blockIdx.z, m0 = blockIdx.y * 128, n0 = blockIdx.x * 128;

    if (n0 >= read_len(slen32, b)) return;

    const int tid = threadIdx.x, lane = tid & 31, wid = tid >> 5;
    const int m_base = (wid >> 2) * 64, n_base = (wid & 3) * 32;

    const unsigned sb = smem_u32(dsm);
    const unsigned st[2] = { sb, sb + STG1 };

    const __half* Ah = g_dec16_hi + (size_t)m0 * LDA + (size_t)b * HID;
    const __half* Al = g_dec16_lo + (size_t)m0 * LDA + (size_t)b * HID;
    const __half* Bh = g_enc16_hi + (size_t)n0 * LDA + (size_t)b * HID;
    const __half* Bl = g_enc16_lo + (size_t)n0 * LDA + (size_t)b * HID;
    const int NC = HID / 32;

    cpa_nt(st[0] + T_AH, Ah, LDA, tid);
    cpa_nt(st[0] + T_AL, Al, LDA, tid);
    cpa_nt(st[0] + T_BH, Bh, LDA, tid);
    cpa_nt(st[0] + T_BL, Bl, LDA, tid);
    cp_commit();

    float acc[4][4][4] = {};
    for (int m = 0; m < NC; ++m) {
        const int s = m & 1;
        if (m + 1 < NC) {
            const int j = (m + 1) & 1;
            const size_t kb = (size_t)(m + 1) * 32;
            cpa_nt(st[j] + T_AH, Ah + kb, LDA, tid);
            cpa_nt(st[j] + T_AL, Al + kb, LDA, tid);
            cpa_nt(st[j] + T_BH, Bh + kb, LDA, tid);
            cpa_nt(st[j] + T_BL, Bl + kb, LDA, tid);
            cp_commit();
            cp_wait<1>();
        } else {
            cp_wait<0>();
        }
        __syncthreads();
        mma_chunk3(dsm + (st[s] - sb) + T_AH, dsm + (st[s] - sb) + T_AL,
                   dsm + (st[s] - sb) + T_BH, dsm + (st[s] - sb) + T_BL,
                   acc, lane, m_base, n_base);
        __syncthreads();
    }

    float* C = scores + (size_t)b * TLEN * SLEN;
    const int r0 = lane >> 2, c0 = (lane & 3) * 2;
#pragma unroll
    for (int i = 0; i < 4; ++i)
#pragma unroll
        for (int j = 0; j < 4; ++j) {
            const int row = m0 + m_base + 16 * i + r0;
            const int col = n0 + n_base + 8 * j + c0;
            *reinterpret_cast<float2*>(C + (size_t)row * SLEN + col)
                = make_float2(acc[i][j][0], acc[i][j][1]);
            *reinterpret_cast<float2*>(C + (size_t)(row + 8) * SLEN + col)
                = make_float2(acc[i][j][2], acc[i][j][3]);
        }
}

// ---------------------------------------------------------------------------
// Masked softmax over S, in place; emits fp16 attn (hi only).
// Shuffle-based reductions (2 __syncthreads total). For the fully-masked
// upper half-row: global LOADS are skipped AND fp16 attn STORES are skipped
// (GEMM2 truncates K at len, so that region is never read). The fp32 output
// writes always happen (poison must become exact zeros).
// ---------------------------------------------------------------------------
__global__ __launch_bounds__(256)
void softmax_rows(float* __restrict__ scores, const int* __restrict__ slen32)
{
    __shared__ float red[8];
    __shared__ int s_len;

    const int row = blockIdx.x;
    const int b = row / TLEN;
    const int tid = threadIdx.x;
    const int lane = tid & 31, wrp = tid >> 5;

    if (tid == 0) s_len = read_len(slen32, b);
    __syncthreads();
    const int len = s_len;
    const bool hi_live = ((tid + 256) * 4 < len);

    float* p = scores + (size_t)row * SLEN;
    float4 v0 = reinterpret_cast<const float4*>(p)[tid];
    float4 v1 = hi_live ? reinterpret_cast<const float4*>(p)[tid + 256]
                        : make_float4(0.f, 0.f, 0.f, 0.f);

    float e[8] = { v0.x, v0.y, v0.z, v0.w, v1.x, v1.y, v1.z, v1.w };
    int s[8];
#pragma unroll
    for (int q = 0; q < 4; ++q) { s[q] = tid * 4 + q; s[4 + q] = (tid + 256) * 4 + q; }

    // --- row max (warp shuffle + 8-wide smem stage) ---
    float m = -1e30f;
#pragma unroll
    for (int q = 0; q < 8; ++q) if (s[q] < len) m = fmaxf(m, e[q]);
#pragma unroll
    for (int off = 16; off > 0; off >>= 1)
        m = fmaxf(m, __shfl_xor_sync(0xffffffffu, m, off));
    if (lane == 0) red[wrp] = m;
    __syncthreads();
    float rowmax = red[lane & 7];
#pragma unroll
    for (int off = 4; off > 0; off >>= 1)
        rowmax = fmaxf(rowmax, __shfl_xor_sync(0xffffffffu, rowmax, off));
    rowmax = __shfl_sync(0xffffffffu, rowmax, 0);

    // --- exp & sum ---
    float sum = 0.f;
#pragma unroll
    for (int q = 0; q < 8; ++q) {
        float ev = (s[q] < len) ? __expf(e[q] - rowmax) : 0.f;
        e[q] = ev; sum += ev;
    }
#pragma unroll
    for (int off = 16; off > 0; off >>= 1)
        sum += __shfl_xor_sync(0xffffffffu, sum, off);
    __syncthreads();
    if (lane == 0) red[wrp] = sum;
    __syncthreads();
    float tot = red[lane & 7];
#pragma unroll
    for (int off = 4; off > 0; off >>= 1)
        tot += __shfl_xor_sync(0xffffffffu, tot, off);
    tot = __shfl_sync(0xffffffffu, tot, 0);
    const float inv = 1.f / tot;

#pragma unroll
    for (int q = 0; q < 8; ++q) e[q] *= inv;

    reinterpret_cast<float4*>(p)[tid]       = make_float4(e[0], e[1], e[2], e[3]);
    reinterpret_cast<float4*>(p)[tid + 256] = make_float4(e[4], e[5], e[6], e[7]);

    __half2* ph = reinterpret_cast<__half2*>(g_attn16 + (size_t)row * SLEN);
    ph[tid * 2]     = __halves2half2(__float2half(e[0]), __float2half(e[1]));
    ph[tid * 2 + 1] = __halves2half2(__float2half(e[2]), __float2half(e[3]));
    if (hi_live) {
        ph[(tid + 256) * 2]     = __halves2half2(__float2half(e[4]), __float2half(e[5]));
        ph[(tid + 256) * 2 + 1] = __halves2half2(__float2half(e[6]), __float2half(e[7]));
    }
}

// ---------------------------------------------------------------------------
// GEMM2: ctx = attn . enc (fp16 1-term). K=32 chunks, double-buffered;
// K truncated at ceil(len/32).
// ---------------------------------------------------------------------------
__global__ __launch_bounds__(256, 2)
void gemm2_ctx(const int* __restrict__ slen32)
{
    extern __shared__ __align__(16) char dsm[];
    const int b = blockIdx.z, m0 = blockIdx.y * 128, n0 = blockIdx.x * 128;
    const int tid = threadIdx.x, lane = tid & 31, wid = tid >> 5;
    const int m_base = (wid >> 2) * 64, n_base = (wid & 3) * 32;

    const unsigned sb = smem_u32(dsm);
    const unsigned st[2] = { sb, sb + STG2 };

    const __half* Av = g_attn16 + (size_t)b * TLEN * SLEN + (size_t)m0 * SLEN;
    const __half* Bv = g_enc16_hi + (size_t)b * HID + n0;   // rows along s (stride LDA)
    const int NC = (read_len(slen32, b) + 31) / 32;

    cpa_nt(st[0], Av, SLEN, tid);
    cpa_tr(st[0] + S2_B, Bv, LDA, tid);
    cp_commit();

    float acc[4][4][4] = {};
    for (int m = 0; m < NC; ++m) {
        const int s = m & 1;
        if (m + 1 < NC) {
            const int j = (m + 1) & 1;
            const size_t kb = (size_t)(m + 1) * 32;
            cpa_nt(st[j], Av + kb, SLEN, tid);
            cpa_tr(st[j] + S2_B, Bv + kb * LDA, LDA, tid);
            cp_commit();
            cp_wait<1>();
        } else {
            cp_wait<0>();
        }
        __syncthreads();
        mma_chunk1<true>(dsm + (st[s] - sb), dsm + (st[s] - sb) + S2_B,
                         acc, lane, m_base, n_base);
        __syncthreads();
    }

    const int r0 = lane >> 2, c0 = (lane & 3) * 2;
#pragma unroll
    for (int i = 0; i < 4; ++i)
#pragma unroll
        for (int j = 0; j < 4; ++j) {
            const int mrow = m0 + m_base + 16 * i + r0;
            const int col = n0 + n_base + 8 * j + c0;
#pragma unroll
            for (int hh = 0; hh < 2; ++hh) {
                const size_t off = (size_t)b * HID + (size_t)(mrow + 8 * hh) * LDA + col;
                *reinterpret_cast<__half2*>(g_ctx16 + off) = __halves2half2(
                    __float2half(acc[i][j][2 * hh]), __float2half(acc[i][j][2 * hh + 1]));
            }
        }
}

// ---------------------------------------------------------------------------
// GEMM3: states = tanh(concat(ctx,dec) . W^T + bias) (fp16 1-term,
// K=32 chunks, double-buffered)
// ---------------------------------------------------------------------------
__global__ __launch_bounds__(256, 2)
void gemm3_out(const float* __restrict__ bias, float* __restrict__ outp)
{
    extern __shared__ __align__(16) char dsm[];
    const int m0 = blockIdx.y * 128, n0 = blockIdx.x * 128;
    const int tid = threadIdx.x, lane = tid & 31, wid = tid >> 5;
    const int m_base = (wid >> 2) * 64, n_base = (wid & 3) * 32;

    const unsigned sb = smem_u32(dsm);
    const unsigned st[2] = { sb, sb + STG3 };

    const __half* Ctx = g_ctx16 + (size_t)m0 * HID;
    const __half* Dec = g_dec16_hi + (size_t)m0 * HID;
    const __half* Bv = g_W16 + (size_t)n0 * (2 * HID);
    const int NC = (2 * HID) / 32;

    cpa_nt(st[0], Ctx, HID, tid);
    cpa_nt(st[0] + S3_B, Bv, 2 * HID, tid);
    cp_commit();

    float acc[4][4][4] = {};
    for (int m = 0; m < NC; ++m) {
        const int s = m & 1;
        if (m + 1 < NC) {
            const int j = (m + 1) & 1;
            const int kb = (m + 1) * 32;
            const __half* pa = (kb < HID) ? (Ctx + kb) : (Dec + (kb - HID));
            cpa_nt(st[j], pa, HID, tid);
            cpa_nt(st[j] + S3_B, Bv + kb, 2 * HID, tid);
            cp_commit();
            cp_wait<1>();
        } else {
            cp_wait<0>();
        }
        __syncthreads();
        mma_chunk1<false>(dsm + (st[s] - sb), dsm + (st[s] - sb) + S3_B,
                          acc, lane, m_base, n_base);
        __syncthreads();
    }

    const int r0 = lane >> 2, c0 = (lane & 3) * 2;
#pragma unroll
    for (int i = 0; i < 4; ++i)
#pragma unroll
        for (int j = 0; j < 4; ++j) {
            const int row = m0 + m_base + 16 * i + r0;
            const int col = n0 + n_base + 8 * j + c0;
            const float b0 = bias[col], b1 = bias[col + 1];
            *reinterpret_cast<float2*>(outp + (size_t)row * HID + col)
                = make_float2(tanhf(acc[i][j][0] + b0), tanhf(acc[i][j][1] + b1));
            *reinterpret_cast<float2*>(outp + (size_t)(row + 8) * HID + col)
                = make_float2(tanhf(acc[i][j][2] + b0), tanhf(acc[i][j][3] + b1));
        }
}

// ---------------------------------------------------------------------------
// kernel_launch — inputs identified by element count (order-proof)
// ---------------------------------------------------------------------------
extern "C" void kernel_launch(void* const* d_in, const int* in_sizes, int n_in,
                              void* d_out, int out_size)
{
    const float* ctxt = nullptr;
    const int*   slen = nullptr;
    const float* dec  = nullptr;
    const float* W    = nullptr;
    const float* bias = nullptr;

    for (int i = 0; i < n_in; ++i) {
        switch (in_sizes[i]) {
            case SLEN * NB * HID: ctxt = (const float*)d_in[i]; break;
            case TLEN * NB * HID: dec  = (const float*)d_in[i]; break;
            case HID * 2 * HID:   W    = (const float*)d_in[i]; break;
            case HID:             bias = (const float*)d_in[i]; break;
            case NB:              slen = (const int*)d_in[i];   break;
        }
    }

    float* outp   = (float*)d_out;
    float* states = outp;                              // [T,B,H]
    float* attn   = outp + (size_t)TLEN * NB * HID;    // [B,T,S]

    const int smem_g1 = 2 * STG1;  // 81920
    const int smem_g2 = 2 * STG2;  // 37888
    const int smem_g3 = 2 * STG3;  // 40960
    cudaFuncSetAttribute(gemm1_scores, cudaFuncAttributeMaxDynamicSharedMemorySize, smem_g1);
    cudaFuncSetAttribute(gemm2_ctx,    cudaFuncAttributeMaxDynamicSharedMemorySize, smem_g2);
    cudaFuncSetAttribute(gemm3_out,    cudaFuncAttributeMaxDynamicSharedMemorySize, smem_g3);

    __half *enc_h, *enc_l, *dec_h, *dec_l, *w16;
    cudaGetSymbolAddress((void**)&enc_h, g_enc16_hi);
    cudaGetSymbolAddress((void**)&enc_l, g_enc16_lo);
    cudaGetSymbolAddress((void**)&dec_h, g_dec16_hi);
    cudaGetSymbolAddress((void**)&dec_l, g_dec16_lo);
    cudaGetSymbolAddress((void**)&w16,   g_W16);

    // 1) splits
    {
        int n4 = (SLEN * NB * HID) / 4;
        split_hl<<<n4 / 256, 256>>>((const float4*)ctxt, (__half2*)enc_h, (__half2*)enc_l, n4);
        n4 = (TLEN * NB * HID) / 4;
        split_hl<<<n4 / 256, 256>>>((const float4*)dec, (__half2*)dec_h, (__half2*)dec_l, n4);
        n4 = (HID * 2 * HID) / 4;
        split_h<<<n4 / 256, 256>>>((const float4*)W, (__half2*)w16, n4);
    }

    // 2) scores -> attn region (masked n-tiles skipped)
    gemm1_scores<<<dim3(SLEN / 128, TLEN / 128, NB), 256, smem_g1>>>(attn, slen);

    // 3) masked softmax in place + attn fp16 (masked loads AND dead fp16 stores skipped)
    softmax_rows<<<NB * TLEN, 256>>>(attn, slen);

    // 4) ctx = attn @ enc (fp16 1-term; K truncated at src_length)
    gemm2_ctx<<<dim3(HID / 128, TLEN / 128, NB), 256, smem_g2>>>(slen);

    // 5) states = tanh(concat(ctx,dec) @ W^T + b) (fp16 1-term)
    gemm3_out<<<dim3(HID / 128, (TLEN * NB) / 128), 256, smem_g3>>>(bias, states);
}